// round 10
// baseline (speedup 1.0000x reference)
#include <cuda_runtime.h>
#include <cstdint>
#include <cstddef>

// Problem constants (fixed by the reference setup_inputs)
#define NN 16384
#define DD 64
#define EE 524288

// Scratch (static __device__ globals — no allocation anywhere)
__device__ __align__(256) float g_deg[NN];
__device__ __align__(256) float g_dinv[NN];
__device__ __align__(256) float g_hs[NN * DD];   // (z@W)*dinv[row]
__device__ __align__(256) float g_acc[NN * DD];  // scatter accumulator
__device__ __align__(256) float g_hr[NN * DD];   // relu(GCN output)
__device__ int g_i64;                            // 1 if edge_index is int64

// ---------------------------------------------------------------------------
// Step 0: detect edge_index dtype. JAX downcasts int64->int32 unless x64 is
// enabled, so int32 is expected; if the data were genuine little-endian int64
// (values < 2^31), every odd int32 word would be zero.
// ---------------------------------------------------------------------------
__global__ void k_detect(const int* __restrict__ ei) {
    if (threadIdx.x == 0) {
        int allzero = 1;
        for (int i = 1; i < 256; i += 2) allzero &= (ei[i] == 0);
        g_i64 = allzero;
    }
}

__device__ __forceinline__ int edge_row(const int* ei, int i64, unsigned e) {
    return i64 ? ei[2u * e] : ei[e];
}
__device__ __forceinline__ int edge_col(const int* ei, int i64, unsigned e) {
    return i64 ? ei[2u * (EE + e)] : ei[EE + e];
}

// ---------------------------------------------------------------------------
// Step 1: degree init (self-loop counts as 1)
// ---------------------------------------------------------------------------
__global__ void k_init_deg() {
    int i = blockIdx.x * blockDim.x + threadIdx.x;
    if (i < NN) g_deg[i] = 1.0f;
}

// Step 2: in-degree count over col (target) indices
__global__ void k_count(const int* __restrict__ ei) {
    unsigned e = blockIdx.x * blockDim.x + threadIdx.x;
    if (e < EE) {
        int c = edge_col(ei, g_i64, e);
        atomicAdd(&g_deg[c], 1.0f);
    }
}

// Step 3: dinv = rsqrt(deg)
__global__ void k_dinv() {
    int i = blockIdx.x * blockDim.x + threadIdx.x;
    if (i < NN) g_dinv[i] = rsqrtf(g_deg[i]);
}

// ---------------------------------------------------------------------------
// Step 4: hs = (z @ W) * dinv[row]; acc initialized to hs (self-loop term)
// ---------------------------------------------------------------------------
__global__ void k_linear(const float* __restrict__ z, const float* __restrict__ W) {
    __shared__ float Ws[DD * DD];
    __shared__ float Zs[32 * DD];
    int t = threadIdx.x;
    int row0 = blockIdx.x * 32;
    for (int i = t; i < DD * DD; i += 256) Ws[i] = W[i];
    for (int i = t; i < 32 * DD; i += 256) Zs[i] = z[(size_t)row0 * DD + i];
    __syncthreads();

    int r  = t >> 3;
    int cg = (t & 7) * 8;
    float acc[8];
#pragma unroll
    for (int c = 0; c < 8; c++) acc[c] = 0.0f;
#pragma unroll
    for (int k = 0; k < DD; k++) {
        float zk = Zs[r * DD + k];
#pragma unroll
        for (int c = 0; c < 8; c++)
            acc[c] = fmaf(zk, Ws[k * DD + cg + c], acc[c]);
    }
    float di = g_dinv[row0 + r];
    size_t base = (size_t)(row0 + r) * DD + cg;
#pragma unroll
    for (int c = 0; c < 8; c++) {
        float v = acc[c] * di;
        g_hs[base + c]  = v;
        g_acc[base + c] = v;
    }
}

// ---------------------------------------------------------------------------
// Step 5: scatter — acc[col*64+d] += hs[row*64+d]; one thread per
// (edge, feature); scalar float atomics.
// ---------------------------------------------------------------------------
__global__ void k_scatter(const int* __restrict__ ei) {
    unsigned tid = blockIdx.x * blockDim.x + threadIdx.x;
    unsigned e = tid >> 6;
    unsigned d = tid & 63;
    if (e >= EE) return;
    int i64 = g_i64;
    int r = edge_row(ei, i64, e);
    int c = edge_col(ei, i64, e);
    float v = g_hs[(size_t)r * DD + d];
    atomicAdd(&g_acc[(size_t)c * DD + d], v);
}

// Step 6: hr = relu(dinv[c] * acc + b)
__global__ void k_final(const float* __restrict__ b) {
    int i = blockIdx.x * blockDim.x + threadIdx.x;
    if (i < NN * DD) {
        int v = i >> 6;
        int d = i & 63;
        g_hr[i] = fmaxf(fmaf(g_dinv[v], g_acc[i], b[d]), 0.0f);
    }
}

// ---------------------------------------------------------------------------
// Step 7: C = hr @ hr^T (symmetric). Upper-triangle block tiles only; mirror
// tile written via shared-memory transpose. 128x128 tile, 256 threads,
// 8x8 micro-tile, K=64 in two 32-chunks. fma.rn.f32x2 packed fp32.
// Static shared memory only: 12288 floats = 49152 B.
// ---------------------------------------------------------------------------
#define FMA2(d, a, b) asm("fma.rn.f32x2 %0, %1, %2, %0;" : "+l"(d) : "l"(a), "l"(b))

union F4U {
    float4 f;
    unsigned long long u[2];
    float s[4];
};

__global__ void __launch_bounds__(256, 2) k_gemm(float* __restrict__ C) {
    int bx = blockIdx.x, by = blockIdx.y;
    if (by > bx) return;   // upper triangle only

    __shared__ float sh[12288];       // 49152 bytes
    float2* Ad = reinterpret_cast<float2*>(sh);  // [32][128] float2 dup: 32 KB
    float*  Bs = sh + 8192;                      // [32][128] float:     16 KB

    int t  = threadIdx.x;
    int tx = t & 15;                  // n-group (8 cols)
    int ty = t >> 4;                  // m-group (8 rows)

    const float4* H4 = reinterpret_cast<const float4*>(g_hr);

    unsigned long long acc[32];       // acc[m*4+np] = f32x2 over cols (n, n+1)
#pragma unroll
    for (int i = 0; i < 32; i++) acc[i] = 0ULL;

    for (int kc = 0; kc < 2; kc++) {
        if (kc) __syncthreads();
        // Stage A rows (by) duplicated, B rows (bx) plain, k-major
        for (int i = t; i < 1024; i += 256) {
            int row = i >> 3;         // 0..127
            int q   = i & 7;          // float4 index within 32-float chunk
            float4 va = H4[(size_t)(by * 128 + row) * 16 + kc * 8 + q];
            Ad[(q * 4 + 0) * 128 + row] = make_float2(va.x, va.x);
            Ad[(q * 4 + 1) * 128 + row] = make_float2(va.y, va.y);
            Ad[(q * 4 + 2) * 128 + row] = make_float2(va.z, va.z);
            Ad[(q * 4 + 3) * 128 + row] = make_float2(va.w, va.w);
            float4 vb = H4[(size_t)(bx * 128 + row) * 16 + kc * 8 + q];
            Bs[(q * 4 + 0) * 128 + row] = vb.x;
            Bs[(q * 4 + 1) * 128 + row] = vb.y;
            Bs[(q * 4 + 2) * 128 + row] = vb.z;
            Bs[(q * 4 + 3) * 128 + row] = vb.w;
        }
        __syncthreads();

#pragma unroll 4
        for (int k = 0; k < 32; k++) {
            const F4U* ap = reinterpret_cast<const F4U*>(&Ad[k * 128 + ty * 8]);
            F4U a0 = ap[0], a1 = ap[1], a2 = ap[2], a3 = ap[3];
            const F4U* bp = reinterpret_cast<const F4U*>(&Bs[k * 128 + tx * 8]);
            F4U b0 = bp[0], b1 = bp[1];
            unsigned long long av[8] = {a0.u[0], a0.u[1], a1.u[0], a1.u[1],
                                        a2.u[0], a2.u[1], a3.u[0], a3.u[1]};
            unsigned long long bv[4] = {b0.u[0], b0.u[1], b1.u[0], b1.u[1]};
#pragma unroll
            for (int m = 0; m < 8; m++)
#pragma unroll
                for (int np = 0; np < 4; np++)
                    FMA2(acc[m * 4 + np], av[m], bv[np]);
        }
    }

    // Upper tile write: coalesced float4 stores
    {
        size_t base = (size_t)(by * 128 + ty * 8) * NN + (size_t)bx * 128 + tx * 8;
#pragma unroll
        for (int m = 0; m < 8; m++) {
            F4U o0, o1;
            o0.u[0] = acc[m * 4 + 0]; o0.u[1] = acc[m * 4 + 1];
            o1.u[0] = acc[m * 4 + 2]; o1.u[1] = acc[m * 4 + 3];
            float4* p = reinterpret_cast<float4*>(&C[base + (size_t)m * NN]);
            p[0] = o0.f;
            p[1] = o1.f;
        }
    }

    if (bx == by) return;

    // Mirror (lower) tile via shared transpose, two 64-column passes.
    float* Ts = sh;   // [128][67] = 8576 floats
    for (int p = 0; p < 2; p++) {
        __syncthreads();
        if ((ty >> 3) == p) {
            int tyl = ty & 7;
#pragma unroll
            for (int m = 0; m < 8; m++)
#pragma unroll
                for (int np = 0; np < 4; np++) {
                    F4U tmp; tmp.u[0] = acc[m * 4 + np];
                    Ts[(tx * 8 + np * 2 + 0) * 67 + tyl * 8 + m] = tmp.s[0];
                    Ts[(tx * 8 + np * 2 + 1) * 67 + tyl * 8 + m] = tmp.s[1];
                }
        }
        __syncthreads();
        for (int i = t; i < 8192; i += 256) {
            int n  = i >> 6;          // 0..127
            int mm = i & 63;          // 0..63
            C[(size_t)(bx * 128 + n) * NN + (size_t)(by * 128) + p * 64 + mm] =
                Ts[n * 67 + mm];
        }
    }
}

// ---------------------------------------------------------------------------
extern "C" void kernel_launch(void* const* d_in, const int* in_sizes, int n_in,
                              void* d_out, int out_size) {
    const float* z  = (const float*)d_in[0];
    const int*   ei = (const int*)d_in[1];   // edge_index (int32; JAX x64 off)
    const float* W  = (const float*)d_in[2];
    const float* b  = (const float*)d_in[3];
    float*       C  = (float*)d_out;

    (void)in_sizes; (void)n_in; (void)out_size;

    k_detect<<<1, 32>>>(ei);
    k_init_deg<<<NN / 256, 256>>>();
    k_count<<<EE / 256, 256>>>(ei);
    k_dinv<<<NN / 256, 256>>>();
    k_linear<<<NN / 32, 256>>>(z, W);
    k_scatter<<<(EE * 64) / 256, 256>>>(ei);
    k_final<<<(NN * DD) / 256, 256>>>(b);

    dim3 grid(NN / 128, NN / 128);
    k_gemm<<<grid, 256>>>(C);
}